// round 14
// baseline (speedup 1.0000x reference)
#include <cuda_runtime.h>
#include <cuda_bf16.h>
#include <cstdint>

#define BATCH 16
#define LP    2048
#define LQ    2048
#define HID   1024

#define TM 128
#define TN 128
#define KS 32
#define TILE_B  (128 * 64)            // 8192 B per tile (both layouts)
#define STAGE_B (4 * TILE_B)          // 32768 B per stage (Ah, Al, Bh, Bl)
#define NSTAGE 3
#define SMEM_BYTES (NSTAGE * STAGE_B) // 98304 -> 2 CTAs/SM
#define PGRID 296                     // persistent grid (<= 2 CTAs/SM on 148 SMs)

typedef __nv_bfloat16 bf16;

// ---------------- persistent scratch (allocation-free) ----------------
__device__ __align__(256) bf16 g_ph [(size_t)BATCH * LP * HID];
__device__ __align__(256) bf16 g_pl [(size_t)BATCH * LP * HID];
__device__ __align__(256) bf16 g_qh [(size_t)BATCH * LQ * HID];
__device__ __align__(256) bf16 g_ql [(size_t)BATCH * LQ * HID];
__device__ __align__(256) bf16 g_wh [(size_t)HID * HID];
__device__ __align__(256) bf16 g_wl [(size_t)HID * HID];
__device__ __align__(256) bf16 g_tqh[(size_t)BATCH * LQ * HID];  // trans_q split
__device__ __align__(256) bf16 g_tql[(size_t)BATCH * LQ * HID];
__device__ __align__(256) float g_att[(size_t)BATCH * LP * LQ];
__device__ __align__(256) bf16 g_ah [(size_t)BATCH * LP * LQ];
__device__ __align__(256) bf16 g_al [(size_t)BATCH * LP * LQ];

// ------------------------- helpers -------------------------
__device__ __forceinline__ uint32_t smem_u32(const void* p) {
    uint32_t a;
    asm("{ .reg .u64 t; cvta.to.shared.u64 t, %1; cvt.u32.u64 %0, t; }"
        : "=r"(a) : "l"(p));
    return a;
}
// [128 rows x 64B] tile: swizzled byte offset of 16B chunk ch (0..3) of row r
__device__ __forceinline__ uint32_t sw_off(uint32_t r, uint32_t ch) {
    return ((r >> 1) << 7) | (((ch ^ ((r & 1) << 2) ^ ((r >> 1) & 3)) & 7) << 4);
}
// [32 rows x 256B] tile: swizzled byte offset of 16B chunk c (0..15) of row r
__device__ __forceinline__ uint32_t swt_off(uint32_t r, uint32_t c) {
    return (r << 8) | ((((c ^ r) & 7) | (c & 8)) << 4);
}
// packs: upper16 = bf16(hi), lower16 = bf16(lo)
__device__ __forceinline__ uint32_t cvt_pair(float hi, float lo) {
    uint32_t r;
    asm("cvt.rn.bf16x2.f32 %0, %1, %2;" : "=r"(r) : "f"(hi), "f"(lo));
    return r;
}
__device__ __forceinline__ void ldsm4(uint32_t* r, uint32_t addr) {
    asm volatile("ldmatrix.sync.aligned.m8n8.x4.shared.b16 {%0,%1,%2,%3}, [%4];"
                 : "=r"(r[0]), "=r"(r[1]), "=r"(r[2]), "=r"(r[3]) : "r"(addr));
}
__device__ __forceinline__ void ldsm4t(uint32_t* r, uint32_t addr) {
    asm volatile("ldmatrix.sync.aligned.m8n8.x4.trans.shared.b16 {%0,%1,%2,%3}, [%4];"
                 : "=r"(r[0]), "=r"(r[1]), "=r"(r[2]), "=r"(r[3]) : "r"(addr));
}
__device__ __forceinline__ void mma16816(float* c, const uint32_t* a,
                                         uint32_t b0, uint32_t b1) {
    asm volatile(
        "mma.sync.aligned.m16n8k16.row.col.f32.bf16.bf16.f32 "
        "{%0,%1,%2,%3}, {%4,%5,%6,%7}, {%8,%9}, {%0,%1,%2,%3};"
        : "+f"(c[0]), "+f"(c[1]), "+f"(c[2]), "+f"(c[3])
        : "r"(a[0]), "r"(a[1]), "r"(a[2]), "r"(a[3]), "r"(b0), "r"(b1));
}
__device__ __forceinline__ void cpasync16(uint32_t saddr, const void* g) {
    asm volatile("cp.async.cg.shared.global [%0], [%1], 16;"
                 :: "r"(saddr), "l"(g) : "memory");
}
// split two floats -> (hiWord, loWord) packed bf16x2
__device__ __forceinline__ void split2(float v0, float v1, uint32_t& h, uint32_t& l) {
    h = cvt_pair(v1, v0);
    float f0 = __uint_as_float(h << 16);
    float f1 = __uint_as_float(h & 0xffff0000u);
    l = cvt_pair(v1 - f1, v0 - f0);
}

// ---------------------------------------------------------------------------
// Persistent bf16x3 HMMA GEMM: static tile striding (tile = bid + k*gridDim),
// continuous cp.async pipeline ACROSS tiles (prologue/epilogue hidden),
// swizzled smem, 3-stage, one sync/stage. 2 CTAs/SM.
// BTR=false: B is [N,K] (k contiguous).  BTR=true: B is [K,N], ldmatrix.trans.
// C[M,N] = (Ah+Al)[M,K] * B^T (+bias)(+ReLU)
// ---------------------------------------------------------------------------
template <bool BIAS, bool RELU, bool OSPLIT, bool BTR>
__global__ void __launch_bounds__(256, 2)
mm_persist(const bf16* __restrict__ Ah, const bf16* __restrict__ Al,
           const bf16* __restrict__ Bh, const bf16* __restrict__ Bl,
           const float* __restrict__ bias,
           float* __restrict__ Cf, bf16* __restrict__ Chi, bf16* __restrict__ Clo,
           int K, int lda, int ldb, int ldc,
           long long sA, long long sB, long long sC,
           int nx, int nxy, int ntiles)
{
    extern __shared__ uint8_t sm[];
    const uint32_t smem = smem_u32(sm);
    const int tid  = threadIdx.x;
    const int lane = tid & 31;
    const int wid  = tid >> 5;
    const int wm   = wid & 3;
    const int wn   = wid >> 2;

    const int ns  = K / KS;
    const int G   = gridDim.x;
    const int nlt = (ntiles - (int)blockIdx.x + G - 1) / G;   // local tiles
    const int nst = nlt * ns;                                  // local stages

    // ---- per-thread loader constants (tile-independent) ----
    const int arow = tid >> 2;
    const int ach  = tid & 3;
    const uint32_t aso0 = sw_off((uint32_t)arow,      (uint32_t)ach);
    const uint32_t aso1 = sw_off((uint32_t)arow + 64, (uint32_t)ach);
    int browt, bct;
    uint32_t bso0, bso1;
    if (BTR) { browt = tid >> 4; bct = tid & 15;
               bso0 = swt_off((uint32_t)browt, (uint32_t)bct);
               bso1 = swt_off((uint32_t)browt + 16, (uint32_t)bct); }
    else     { browt = tid >> 2; bct = tid & 3;
               bso0 = sw_off((uint32_t)browt, (uint32_t)bct);
               bso1 = sw_off((uint32_t)browt + 64, (uint32_t)bct); }

    // issue global stage j (local tile = j/ns); commits empty group past end
    auto issue = [&](int j) {
        if (j < nst) {
            const int lt = j / ns;
            const int s  = j - lt * ns;
            const int t  = (int)blockIdx.x + lt * G;
            const int z  = t / nxy;
            const int r  = t - z * nxy;
            const int ty = r / nx;
            const int tx = r - ty * nx;
            const long long ko = (long long)s * KS;
            const uint32_t b = smem + (uint32_t)(j % NSTAGE) * STAGE_B;

            const long long aoff = sA * z + (long long)(ty * TM + arow) * lda
                                 + ach * 8 + ko;
            cpasync16(b + aso0,          Ah + aoff);
            cpasync16(b + aso1,          Ah + aoff + 64LL * lda);
            cpasync16(b + TILE_B + aso0, Al + aoff);
            cpasync16(b + TILE_B + aso1, Al + aoff + 64LL * lda);
            if (BTR) {
                const long long boff = sB * z + (long long)browt * ldb
                                     + tx * TN + bct * 8 + ko * ldb;
                cpasync16(b + 2 * TILE_B + bso0, Bh + boff);
                cpasync16(b + 2 * TILE_B + bso1, Bh + boff + 16LL * ldb);
                cpasync16(b + 3 * TILE_B + bso0, Bl + boff);
                cpasync16(b + 3 * TILE_B + bso1, Bl + boff + 16LL * ldb);
            } else {
                const long long boff = sB * z + (long long)(tx * TN + browt) * ldb
                                     + bct * 8 + ko;
                cpasync16(b + 2 * TILE_B + bso0, Bh + boff);
                cpasync16(b + 2 * TILE_B + bso1, Bh + boff + 64LL * ldb);
                cpasync16(b + 3 * TILE_B + bso0, Bl + boff);
                cpasync16(b + 3 * TILE_B + bso1, Bl + boff + 64LL * ldb);
            }
        }
        asm volatile("cp.async.commit_group;" ::: "memory");
    };

    issue(0); issue(1);

    // fragment coordinates
    const uint32_t a_r  = (uint32_t)(wm * 32 + (lane & 15));
    const uint32_t a_ch = (uint32_t)((lane >> 4) & 1);
    const uint32_t b_r  = (uint32_t)(wn * 64 + (lane & 7) + ((lane & 16) >> 1)); // !BTR
    const uint32_t b_ch = (uint32_t)((lane >> 3) & 1);                           // !BTR
    const uint32_t bt_r = (uint32_t)(lane & 15);                                 // BTR
    const uint32_t bt_c = (uint32_t)(wn * 8 + (lane >> 4));                      // BTR

    const int g  = lane >> 2;
    const int t4 = lane & 3;

    int j = 0;
    for (int lt = 0; lt < nlt; lt++) {
        float acc[2][8][4];
        #pragma unroll
        for (int i = 0; i < 2; i++)
            #pragma unroll
            for (int jj = 0; jj < 8; jj++)
                #pragma unroll
                for (int r = 0; r < 4; r++) acc[i][jj][r] = 0.f;

        for (int s = 0; s < ns; s++, j++) {
            asm volatile("cp.async.wait_group 1;" ::: "memory");
            __syncthreads();
            issue(j + 2);   // buffer (j+2)%3 == (j-1)%3: consumed before this sync

            const uint32_t base = smem + (uint32_t)(j % NSTAGE) * STAGE_B;
            #pragma unroll
            for (int kk2 = 0; kk2 < 2; kk2++) {
                uint32_t ah[2][4], al[2][4];
                #pragma unroll
                for (int t = 0; t < 2; t++) {
                    const uint32_t o = sw_off(a_r + t * 16, 2 * kk2 + a_ch);
                    ldsm4(ah[t], base + o);
                    ldsm4(al[t], base + TILE_B + o);
                }
                #pragma unroll
                for (int tb = 0; tb < 4; tb++) {
                    uint32_t bh[4], bl[4];
                    if (BTR) {
                        const uint32_t o = swt_off(kk2 * 16 + bt_r, bt_c + tb * 2);
                        ldsm4t(bh, base + 2 * TILE_B + o);
                        ldsm4t(bl, base + 3 * TILE_B + o);
                    } else {
                        const uint32_t o = sw_off(b_r + tb * 16, 2 * kk2 + b_ch);
                        ldsm4(bh, base + 2 * TILE_B + o);
                        ldsm4(bl, base + 3 * TILE_B + o);
                    }
                    #pragma unroll
                    for (int mi = 0; mi < 2; mi++) {
                        mma16816(acc[mi][2 * tb],     ah[mi], bh[0], bh[1]);
                        mma16816(acc[mi][2 * tb],     ah[mi], bl[0], bl[1]);
                        mma16816(acc[mi][2 * tb],     al[mi], bh[0], bh[1]);
                        mma16816(acc[mi][2 * tb + 1], ah[mi], bh[2], bh[3]);
                        mma16816(acc[mi][2 * tb + 1], ah[mi], bl[2], bl[3]);
                        mma16816(acc[mi][2 * tb + 1], al[mi], bh[2], bh[3]);
                    }
                }
            }
        }

        // ---- epilogue for tile lt (next tile's loads already in flight) ----
        {
            const int t  = (int)blockIdx.x + lt * G;
            const int z  = t / nxy;
            const int r  = t - z * nxy;
            const int ty = r / nx;
            const int tx = r - ty * nx;
            const int m0 = ty * TM;
            const int n0 = tx * TN;
            float* cf  = OSPLIT ? nullptr : Cf + sC * z;
            bf16* chi  = OSPLIT ? Chi + sC * z : nullptr;
            bf16* clo  = OSPLIT ? Clo + sC * z : nullptr;
            #pragma unroll
            for (int mi = 0; mi < 2; mi++) {
                #pragma unroll
                for (int ni = 0; ni < 8; ni++) {
                    const int row = m0 + wm * 32 + mi * 16 + g;
                    const int col = n0 + wn * 64 + ni * 8 + t4 * 2;
                    float* c = acc[mi][ni];
                    float b0 = 0.f, b1 = 0.f;
                    if (BIAS) { b0 = __ldg(&bias[col]); b1 = __ldg(&bias[col + 1]); }
                    float v00 = c[0] + b0, v01 = c[1] + b1;
                    float v10 = c[2] + b0, v11 = c[3] + b1;
                    if (RELU) {
                        v00 = fmaxf(v00, 0.f); v01 = fmaxf(v01, 0.f);
                        v10 = fmaxf(v10, 0.f); v11 = fmaxf(v11, 0.f);
                    }
                    if (OSPLIT) {
                        uint32_t h, l;
                        split2(v00, v01, h, l);
                        ((uint32_t*)chi)[((long long)row * ldc + col) >> 1] = h;
                        ((uint32_t*)clo)[((long long)row * ldc + col) >> 1] = l;
                        split2(v10, v11, h, l);
                        ((uint32_t*)chi)[((long long)(row + 8) * ldc + col) >> 1] = h;
                        ((uint32_t*)clo)[((long long)(row + 8) * ldc + col) >> 1] = l;
                    } else {
                        *(float2*)&cf[(long long)row * ldc + col]       = make_float2(v00, v01);
                        *(float2*)&cf[(long long)(row + 8) * ldc + col] = make_float2(v10, v11);
                    }
                }
            }
        }
    }
}

// ---------------------------------------------------------------------------
// Elementwise split: fp32 -> bf16 hi/lo, three tensors in one launch
// ---------------------------------------------------------------------------
__global__ __launch_bounds__(256)
void split3_kernel(const float* __restrict__ in0, bf16* __restrict__ hi0,
                   bf16* __restrict__ lo0,
                   const float* __restrict__ in1, bf16* __restrict__ hi1,
                   bf16* __restrict__ lo1, long long n4a,
                   const float* __restrict__ in2, bf16* __restrict__ hi2,
                   bf16* __restrict__ lo2, long long n4w)
{
    const float* in;
    bf16 *hi, *lo;
    long long n4;
    if (blockIdx.y == 0)      { in = in0; hi = hi0; lo = lo0; n4 = n4a; }
    else if (blockIdx.y == 1) { in = in1; hi = hi1; lo = lo1; n4 = n4a; }
    else                      { in = in2; hi = hi2; lo = lo2; n4 = n4w; }
    const long long stride = (long long)gridDim.x * blockDim.x;
    for (long long i = (long long)blockIdx.x * blockDim.x + threadIdx.x;
         i < n4; i += stride) {
        float4 v = ((const float4*)in)[i];
        uint32_t h01, l01, h23, l23;
        split2(v.x, v.y, h01, l01);
        split2(v.z, v.w, h23, l23);
        ((uint2*)hi)[i] = make_uint2(h01, h23);
        ((uint2*)lo)[i] = make_uint2(l01, l23);
    }
}

// ---------------------------------------------------------------------------
// Row softmax (2048) reading fp32, writing split bf16 hi/lo.
// ---------------------------------------------------------------------------
__global__ __launch_bounds__(256)
void softmax_split(const float* __restrict__ att,
                   bf16* __restrict__ oh, bf16* __restrict__ ol)
{
    const float* row = att + (long long)blockIdx.x * 2048;
    uint32_t* oh32 = (uint32_t*)oh + (long long)blockIdx.x * 1024;
    uint32_t* ol32 = (uint32_t*)ol + (long long)blockIdx.x * 1024;
    const int tid = threadIdx.x;
    const int wid = tid >> 5, lane = tid & 31;

    float2 v[4];
    float m = -3.4e38f;
    #pragma unroll
    for (int i = 0; i < 4; i++) {
        v[i] = ((const float2*)row)[tid + 256 * i];
        m = fmaxf(m, fmaxf(v[i].x, v[i].y));
    }
    #pragma unroll
    for (int o = 16; o > 0; o >>= 1) m = fmaxf(m, __shfl_xor_sync(0xffffffffu, m, o));

    __shared__ float red[8];
    __shared__ float sval;
    if (lane == 0) red[wid] = m;
    __syncthreads();
    if (tid == 0) {
        float t = red[0];
        #pragma unroll
        for (int w = 1; w < 8; w++) t = fmaxf(t, red[w]);
        sval = t;
    }
    __syncthreads();
    m = sval;

    float s = 0.f;
    #pragma unroll
    for (int i = 0; i < 4; i++) {
        v[i].x = expf(v[i].x - m);
        v[i].y = expf(v[i].y - m);
        s += v[i].x + v[i].y;
    }
    #pragma unroll
    for (int o = 16; o > 0; o >>= 1) s += __shfl_xor_sync(0xffffffffu, s, o);
    __syncthreads();
    if (lane == 0) red[wid] = s;
    __syncthreads();
    if (tid == 0) {
        float t = 0.f;
        #pragma unroll
        for (int w = 0; w < 8; w++) t += red[w];
        sval = 1.0f / t;
    }
    __syncthreads();
    const float inv = sval;
    #pragma unroll
    for (int i = 0; i < 4; i++) {
        float x = v[i].x * inv, y = v[i].y * inv;
        uint32_t h, l;
        split2(x, y, h, l);
        oh32[tid + 256 * i] = h;
        ol32[tid + 256 * i] = l;
    }
}

// ---------------------------------------------------------------------------
extern "C" void kernel_launch(void* const* d_in, const int* in_sizes, int n_in,
                              void* d_out, int out_size)
{
    const float* proj_p = (const float*)d_in[0];   // [B, LP, H]
    const float* proj_q = (const float*)d_in[1];   // [B, LQ, H]
    const float* W      = (const float*)d_in[2];   // [H, H]
    const float* bias   = (const float*)d_in[3];   // [H]
    float* out = (float*)d_out;                    // [B, LP, H]

    bf16 *ph, *pl, *qh, *ql, *wh, *wl, *tqh, *tql, *ah, *al;
    float *att;
    cudaGetSymbolAddress((void**)&ph,  g_ph);   cudaGetSymbolAddress((void**)&pl,  g_pl);
    cudaGetSymbolAddress((void**)&qh,  g_qh);   cudaGetSymbolAddress((void**)&ql,  g_ql);
    cudaGetSymbolAddress((void**)&wh,  g_wh);   cudaGetSymbolAddress((void**)&wl,  g_wl);
    cudaGetSymbolAddress((void**)&tqh, g_tqh);  cudaGetSymbolAddress((void**)&tql, g_tql);
    cudaGetSymbolAddress((void**)&ah,  g_ah);   cudaGetSymbolAddress((void**)&al,  g_al);
    cudaGetSymbolAddress((void**)&att, g_att);

    cudaFuncSetAttribute(mm_persist<true,  false, true,  false>,
                         cudaFuncAttributeMaxDynamicSharedMemorySize, SMEM_BYTES);
    cudaFuncSetAttribute(mm_persist<false, false, false, false>,
                         cudaFuncAttributeMaxDynamicSharedMemorySize, SMEM_BYTES);
    cudaFuncSetAttribute(mm_persist<false, true,  false, true >,
                         cudaFuncAttributeMaxDynamicSharedMemorySize, SMEM_BYTES);

    const dim3 blk(256);

    // 0) operand splits (proj_p, proj_q, W in one launch)
    split3_kernel<<<dim3(4096, 3), 256>>>(proj_p, ph, pl, proj_q, qh, ql,
                                          (long long)BATCH * LP * HID / 4,
                                          W, wh, wl, (long long)HID * HID / 4);

    // 1) trans_q = proj_q @ W^T + b  -> split bf16 [B*LQ, H]
    {
        const int nx = HID / TN, ny = (BATCH * LQ) / TM, nz = 1;
        const int nt = nx * ny * nz;
        mm_persist<true, false, true, false>
            <<<(nt < PGRID ? nt : PGRID), blk, SMEM_BYTES>>>(
            qh, ql, wh, wl, bias, nullptr, tqh, tql, HID, HID, HID, HID,
            0, 0, 0, nx, nx * ny, nt);
    }

    // 2) att[b] = proj_p[b] @ trans_q[b]^T  -> fp32 [LP, LQ]
    {
        const int nx = LQ / TN, ny = LP / TM, nz = BATCH;
        const int nt = nx * ny * nz;
        mm_persist<false, false, false, false>
            <<<(nt < PGRID ? nt : PGRID), blk, SMEM_BYTES>>>(
            ph, pl, tqh, tql, nullptr, att, nullptr, nullptr, HID, HID, HID, LQ,
            (long long)LP * HID, (long long)LQ * HID, (long long)LP * LQ,
            nx, nx * ny, nt);
    }

    // 3) softmax -> split bf16
    softmax_split<<<BATCH * LP, 256>>>(att, ah, al);

    // 4) out = relu(att_norm @ trans_q)  (bias folded; B via ldmatrix.trans)
    {
        const int nx = HID / TN, ny = LP / TM, nz = BATCH;
        const int nt = nx * ny * nz;
        mm_persist<false, true, false, true>
            <<<(nt < PGRID ? nt : PGRID), blk, SMEM_BYTES>>>(
            ah, al, tqh, tql, nullptr, out, nullptr, nullptr, LQ, LQ, HID, HID,
            (long long)LP * LQ, (long long)LQ * HID, (long long)LP * HID,
            nx, nx * ny, nt);
    }
}

// round 15
// speedup vs baseline: 1.1197x; 1.1197x over previous
#include <cuda_runtime.h>
#include <cuda_bf16.h>
#include <cstdint>

#define BATCH 16
#define LP    2048
#define LQ    2048
#define HID   1024

#define TM 128
#define TN 128
#define KS 32
#define TILE_B  (128 * 64)            // 8192 B per tile (both layouts)
#define STAGE_B (4 * TILE_B)          // 32768 B per stage (Ah, Al, Bh, Bl)
#define NSTAGE 3
#define SMEM_BYTES (NSTAGE * STAGE_B) // 98304 -> 2 CTAs/SM

typedef __nv_bfloat16 bf16;

// ---------------- persistent scratch (allocation-free) ----------------
__device__ __align__(256) bf16 g_ph [(size_t)BATCH * LP * HID];
__device__ __align__(256) bf16 g_pl [(size_t)BATCH * LP * HID];
__device__ __align__(256) bf16 g_qh [(size_t)BATCH * LQ * HID];
__device__ __align__(256) bf16 g_ql [(size_t)BATCH * LQ * HID];
__device__ __align__(256) bf16 g_wh [(size_t)HID * HID];
__device__ __align__(256) bf16 g_wl [(size_t)HID * HID];
__device__ __align__(256) bf16 g_tqh[(size_t)BATCH * LQ * HID];  // trans_q split
__device__ __align__(256) bf16 g_tql[(size_t)BATCH * LQ * HID];
__device__ __align__(256) float g_att[(size_t)BATCH * LP * LQ];
__device__ __align__(256) bf16 g_ah [(size_t)BATCH * LP * LQ];
__device__ __align__(256) bf16 g_al [(size_t)BATCH * LP * LQ];

// ------------------------- helpers -------------------------
__device__ __forceinline__ uint32_t smem_u32(const void* p) {
    uint32_t a;
    asm("{ .reg .u64 t; cvta.to.shared.u64 t, %1; cvt.u32.u64 %0, t; }"
        : "=r"(a) : "l"(p));
    return a;
}
// [128 rows x 64B] tile: swizzled byte offset of 16B chunk ch (0..3) of row r
__device__ __forceinline__ uint32_t sw_off(uint32_t r, uint32_t ch) {
    return ((r >> 1) << 7) | (((ch ^ ((r & 1) << 2) ^ ((r >> 1) & 3)) & 7) << 4);
}
// [32 rows x 256B] tile: swizzled byte offset of 16B chunk c (0..15) of row r
__device__ __forceinline__ uint32_t swt_off(uint32_t r, uint32_t c) {
    return (r << 8) | ((((c ^ r) & 7) | (c & 8)) << 4);
}
// packs: upper16 = bf16(hi), lower16 = bf16(lo)
__device__ __forceinline__ uint32_t cvt_pair(float hi, float lo) {
    uint32_t r;
    asm("cvt.rn.bf16x2.f32 %0, %1, %2;" : "=r"(r) : "f"(hi), "f"(lo));
    return r;
}
__device__ __forceinline__ void ldsm4(uint32_t* r, uint32_t addr) {
    asm volatile("ldmatrix.sync.aligned.m8n8.x4.shared.b16 {%0,%1,%2,%3}, [%4];"
                 : "=r"(r[0]), "=r"(r[1]), "=r"(r[2]), "=r"(r[3]) : "r"(addr));
}
__device__ __forceinline__ void ldsm4t(uint32_t* r, uint32_t addr) {
    asm volatile("ldmatrix.sync.aligned.m8n8.x4.trans.shared.b16 {%0,%1,%2,%3}, [%4];"
                 : "=r"(r[0]), "=r"(r[1]), "=r"(r[2]), "=r"(r[3]) : "r"(addr));
}
__device__ __forceinline__ void mma16816(float* c, const uint32_t* a,
                                         uint32_t b0, uint32_t b1) {
    asm volatile(
        "mma.sync.aligned.m16n8k16.row.col.f32.bf16.bf16.f32 "
        "{%0,%1,%2,%3}, {%4,%5,%6,%7}, {%8,%9}, {%0,%1,%2,%3};"
        : "+f"(c[0]), "+f"(c[1]), "+f"(c[2]), "+f"(c[3])
        : "r"(a[0]), "r"(a[1]), "r"(a[2]), "r"(a[3]), "r"(b0), "r"(b1));
}
__device__ __forceinline__ void cpasync16(uint32_t saddr, const void* g) {
    asm volatile("cp.async.cg.shared.global [%0], [%1], 16;"
                 :: "r"(saddr), "l"(g) : "memory");
}
// split two floats -> (hiWord, loWord) packed bf16x2
__device__ __forceinline__ void split2(float v0, float v1, uint32_t& h, uint32_t& l) {
    h = cvt_pair(v1, v0);
    float f0 = __uint_as_float(h << 16);
    float f1 = __uint_as_float(h & 0xffff0000u);
    l = cvt_pair(v1 - f1, v0 - f0);
}

// ---------------------------------------------------------------------------
// bf16x3 HMMA GEMM (round-13 core): swizzled smem, 3-stage cp.async pipeline,
// one sync/stage, 2 CTAs/SM.
// FUSE=true: 1-D grid; CTAs with bid >= ntiles run the proj_p split instead
// (overlaps the DRAM-bound split with the tensor-bound GEMM).
// BTR=false: B is [N,K] (k contiguous).  BTR=true: B is [K,N], ldmatrix.trans.
// C[M,N] = (Ah+Al)[M,K] * B^T (+bias)(+ReLU)
// ---------------------------------------------------------------------------
template <bool BIAS, bool RELU, bool OSPLIT, bool BTR, bool FUSE>
__global__ void __launch_bounds__(256, 2)
mm_bf16x3(const bf16* __restrict__ Ah, const bf16* __restrict__ Al,
          const bf16* __restrict__ Bh, const bf16* __restrict__ Bl,
          const float* __restrict__ bias,
          float* __restrict__ Cf, bf16* __restrict__ Chi, bf16* __restrict__ Clo,
          int K, int lda, int ldb, int ldc,
          long long sA, long long sB, long long sC,
          const float* __restrict__ Pin, bf16* __restrict__ Phi,
          bf16* __restrict__ Plo, long long pn4, int nx, int ntiles)
{
    extern __shared__ uint8_t sm[];
    const uint32_t smem = smem_u32(sm);
    const int tid  = threadIdx.x;
    const int lane = tid & 31;
    const int wid  = tid >> 5;
    const int wm   = wid & 3;
    const int wn   = wid >> 2;

    int tx, ty, z;
    if (FUSE) {
        const int bid = (int)blockIdx.x;
        if (bid >= ntiles) {
            // -------- splitter role: fp32 proj_p -> bf16 hi/lo --------
            const long long stride =
                (long long)((int)gridDim.x - ntiles) * blockDim.x;
            for (long long i = (long long)(bid - ntiles) * blockDim.x + tid;
                 i < pn4; i += stride) {
                float4 v = ((const float4*)Pin)[i];
                uint32_t h01, l01, h23, l23;
                split2(v.x, v.y, h01, l01);
                split2(v.z, v.w, h23, l23);
                ((uint2*)Phi)[i] = make_uint2(h01, h23);
                ((uint2*)Plo)[i] = make_uint2(l01, l23);
            }
            return;
        }
        ty = bid / nx;
        tx = bid - ty * nx;
        z  = 0;
    } else {
        tx = (int)blockIdx.x; ty = (int)blockIdx.y; z = (int)blockIdx.z;
    }

    const long long zz = z;
    Ah += sA * zz;  Al += sA * zz;
    Bh += sB * zz;  Bl += sB * zz;
    if (OSPLIT) { Chi += sC * zz; Clo += sC * zz; }
    else        { Cf  += sC * zz; }

    const int m0 = ty * TM;
    const int n0 = tx * TN;

    // ---- cp.async mappings ----
    const int arow = tid >> 2;
    const int ach  = tid & 3;
    const bf16* gAh = Ah + (long long)(m0 + arow) * lda + ach * 8;
    const bf16* gAl = Al + (long long)(m0 + arow) * lda + ach * 8;
    const uint32_t aso0 = sw_off((uint32_t)arow,      (uint32_t)ach);
    const uint32_t aso1 = sw_off((uint32_t)arow + 64, (uint32_t)ach);

    const bf16 *gBh, *gBl;
    uint32_t bso0, bso1;
    long long bstep1;
    if (BTR) {
        const int brow = tid >> 4;          // 0..15 (second chunk: +16)
        const int bc   = tid & 15;
        gBh = Bh + (long long)brow * ldb + n0 + bc * 8;
        gBl = Bl + (long long)brow * ldb + n0 + bc * 8;
        bso0 = swt_off((uint32_t)brow,      (uint32_t)bc);
        bso1 = swt_off((uint32_t)brow + 16, (uint32_t)bc);
        bstep1 = 16LL * ldb;
    } else {
        const int brow = tid >> 2;
        const int bch  = tid & 3;
        gBh = Bh + (long long)(n0 + brow) * ldb + bch * 8;
        gBl = Bl + (long long)(n0 + brow) * ldb + bch * 8;
        bso0 = sw_off((uint32_t)brow,      (uint32_t)bch);
        bso1 = sw_off((uint32_t)brow + 64, (uint32_t)bch);
        bstep1 = 64LL * ldb;
    }

    const int ns = K / KS;

    auto issue = [&](int s) {
        if (s < ns) {
            const uint32_t b = smem + (uint32_t)(s % NSTAGE) * STAGE_B;
            const long long ko = (long long)s * KS;
            cpasync16(b + aso0,          gAh + ko);
            cpasync16(b + aso1,          gAh + ko + 64LL * lda);
            cpasync16(b + TILE_B + aso0, gAl + ko);
            cpasync16(b + TILE_B + aso1, gAl + ko + 64LL * lda);
            const long long bko = BTR ? ko * ldb : ko;
            cpasync16(b + 2 * TILE_B + bso0, gBh + bko);
            cpasync16(b + 2 * TILE_B + bso1, gBh + bko + bstep1);
            cpasync16(b + 3 * TILE_B + bso0, gBl + bko);
            cpasync16(b + 3 * TILE_B + bso1, gBl + bko + bstep1);
        }
        asm volatile("cp.async.commit_group;" ::: "memory");
    };

    issue(0); issue(1);

    // fragment coordinates
    const uint32_t a_r  = (uint32_t)(wm * 32 + (lane & 15));
    const uint32_t a_ch = (uint32_t)((lane >> 4) & 1);
    const uint32_t b_r  = (uint32_t)(wn * 64 + (lane & 7) + ((lane & 16) >> 1)); // !BTR
    const uint32_t b_ch = (uint32_t)((lane >> 3) & 1);                           // !BTR
    const uint32_t bt_r = (uint32_t)(lane & 15);                                 // BTR: k row
    const uint32_t bt_c = (uint32_t)(wn * 8 + (lane >> 4));                      // BTR: chunk

    float acc[2][8][4];
    #pragma unroll
    for (int i = 0; i < 2; i++)
        #pragma unroll
        for (int j = 0; j < 8; j++)
            #pragma unroll
            for (int r = 0; r < 4; r++) acc[i][j][r] = 0.f;

    for (int s = 0; s < ns; s++) {
        asm volatile("cp.async.wait_group 1;" ::: "memory");
        __syncthreads();
        issue(s + 2);   // (s+2)%3 == (s-1)%3: all warps finished it at stage s-1

        const uint32_t base = smem + (uint32_t)(s % NSTAGE) * STAGE_B;
        #pragma unroll
        for (int kk2 = 0; kk2 < 2; kk2++) {
            uint32_t ah[2][4], al[2][4];
            #pragma unroll
            for (int t = 0; t < 2; t++) {
                const uint32_t o = sw_off(a_r + t * 16, 2 * kk2 + a_ch);
                ldsm4(ah[t], base + o);
                ldsm4(al[t], base + TILE_B + o);
            }
            #pragma unroll
            for (int tb = 0; tb < 4; tb++) {
                uint32_t bh[4], bl[4];
                if (BTR) {
                    const uint32_t o = swt_off(kk2 * 16 + bt_r, bt_c + tb * 2);
                    ldsm4t(bh, base + 2 * TILE_B + o);
                    ldsm4t(bl, base + 3 * TILE_B + o);
                } else {
                    const uint32_t o = sw_off(b_r + tb * 16, 2 * kk2 + b_ch);
                    ldsm4(bh, base + 2 * TILE_B + o);
                    ldsm4(bl, base + 3 * TILE_B + o);
                }
                #pragma unroll
                for (int mi = 0; mi < 2; mi++) {
                    mma16816(acc[mi][2 * tb],     ah[mi], bh[0], bh[1]);
                    mma16816(acc[mi][2 * tb],     ah[mi], bl[0], bl[1]);
                    mma16816(acc[mi][2 * tb],     al[mi], bh[0], bh[1]);
                    mma16816(acc[mi][2 * tb + 1], ah[mi], bh[2], bh[3]);
                    mma16816(acc[mi][2 * tb + 1], ah[mi], bl[2], bl[3]);
                    mma16816(acc[mi][2 * tb + 1], al[mi], bh[2], bh[3]);
                }
            }
        }
    }

    // ---- epilogue ----
    const int g  = lane >> 2;
    const int t4 = lane & 3;
    #pragma unroll
    for (int mi = 0; mi < 2; mi++) {
        #pragma unroll
        for (int ni = 0; ni < 8; ni++) {
            const int row = m0 + wm * 32 + mi * 16 + g;
            const int col = n0 + wn * 64 + ni * 8 + t4 * 2;
            float* c = acc[mi][ni];
            float b0 = 0.f, b1 = 0.f;
            if (BIAS) { b0 = __ldg(&bias[col]); b1 = __ldg(&bias[col + 1]); }
            float v00 = c[0] + b0, v01 = c[1] + b1;
            float v10 = c[2] + b0, v11 = c[3] + b1;
            if (RELU) {
                v00 = fmaxf(v00, 0.f); v01 = fmaxf(v01, 0.f);
                v10 = fmaxf(v10, 0.f); v11 = fmaxf(v11, 0.f);
            }
            if (OSPLIT) {
                uint32_t h, l;
                split2(v00, v01, h, l);
                ((uint32_t*)Chi)[((long long)row * ldc + col) >> 1] = h;
                ((uint32_t*)Clo)[((long long)row * ldc + col) >> 1] = l;
                split2(v10, v11, h, l);
                ((uint32_t*)Chi)[((long long)(row + 8) * ldc + col) >> 1] = h;
                ((uint32_t*)Clo)[((long long)(row + 8) * ldc + col) >> 1] = l;
            } else {
                *(float2*)&Cf[(long long)row * ldc + col]       = make_float2(v00, v01);
                *(float2*)&Cf[(long long)(row + 8) * ldc + col] = make_float2(v10, v11);
            }
        }
    }
}

// ---------------------------------------------------------------------------
// Elementwise split: fp32 -> bf16 hi/lo, two tensors in one launch (q, W)
// ---------------------------------------------------------------------------
__global__ __launch_bounds__(256)
void split_qw_kernel(const float* __restrict__ in0, bf16* __restrict__ hi0,
                     bf16* __restrict__ lo0, long long n4q,
                     const float* __restrict__ in1, bf16* __restrict__ hi1,
                     bf16* __restrict__ lo1, long long n4w)
{
    const float* in = blockIdx.y ? in1 : in0;
    bf16* hi = blockIdx.y ? hi1 : hi0;
    bf16* lo = blockIdx.y ? lo1 : lo0;
    const long long n4 = blockIdx.y ? n4w : n4q;
    const long long stride = (long long)gridDim.x * blockDim.x;
    for (long long i = (long long)blockIdx.x * blockDim.x + threadIdx.x;
         i < n4; i += stride) {
        float4 v = ((const float4*)in)[i];
        uint32_t h01, l01, h23, l23;
        split2(v.x, v.y, h01, l01);
        split2(v.z, v.w, h23, l23);
        ((uint2*)hi)[i] = make_uint2(h01, h23);
        ((uint2*)lo)[i] = make_uint2(l01, l23);
    }
}

// ---------------------------------------------------------------------------
// Row softmax (2048) reading fp32, writing split bf16 hi/lo.
// ---------------------------------------------------------------------------
__global__ __launch_bounds__(256)
void softmax_split(const float* __restrict__ att,
                   bf16* __restrict__ oh, bf16* __restrict__ ol)
{
    const float* row = att + (long long)blockIdx.x * 2048;
    uint32_t* oh32 = (uint32_t*)oh + (long long)blockIdx.x * 1024;
    uint32_t* ol32 = (uint32_t*)ol + (long long)blockIdx.x * 1024;
    const int tid = threadIdx.x;
    const int wid = tid >> 5, lane = tid & 31;

    float2 v[4];
    float m = -3.4e38f;
    #pragma unroll
    for (int i = 0; i < 4; i++) {
        v[i] = ((const float2*)row)[tid + 256 * i];
        m = fmaxf(m, fmaxf(v[i].x, v[i].y));
    }
    #pragma unroll
    for (int o = 16; o > 0; o >>= 1) m = fmaxf(m, __shfl_xor_sync(0xffffffffu, m, o));

    __shared__ float red[8];
    __shared__ float sval;
    if (lane == 0) red[wid] = m;
    __syncthreads();
    if (tid == 0) {
        float t = red[0];
        #pragma unroll
        for (int w = 1; w < 8; w++) t = fmaxf(t, red[w]);
        sval = t;
    }
    __syncthreads();
    m = sval;

    float s = 0.f;
    #pragma unroll
    for (int i = 0; i < 4; i++) {
        v[i].x = expf(v[i].x - m);
        v[i].y = expf(v[i].y - m);
        s += v[i].x + v[i].y;
    }
    #pragma unroll
    for (int o = 16; o > 0; o >>= 1) s += __shfl_xor_sync(0xffffffffu, s, o);
    __syncthreads();
    if (lane == 0) red[wid] = s;
    __syncthreads();
    if (tid == 0) {
        float t = 0.f;
        #pragma unroll
        for (int w = 0; w < 8; w++) t += red[w];
        sval = 1.0f / t;
    }
    __syncthreads();
    const float inv = sval;
    #pragma unroll
    for (int i = 0; i < 4; i++) {
        float x = v[i].x * inv, y = v[i].y * inv;
        uint32_t h, l;
        split2(x, y, h, l);
        oh32[tid + 256 * i] = h;
        ol32[tid + 256 * i] = l;
    }
}

// ---------------------------------------------------------------------------
extern "C" void kernel_launch(void* const* d_in, const int* in_sizes, int n_in,
                              void* d_out, int out_size)
{
    const float* proj_p = (const float*)d_in[0];   // [B, LP, H]
    const float* proj_q = (const float*)d_in[1];   // [B, LQ, H]
    const float* W      = (const float*)d_in[2];   // [H, H]
    const float* bias   = (const float*)d_in[3];   // [H]
    float* out = (float*)d_out;                    // [B, LP, H]

    bf16 *ph, *pl, *qh, *ql, *wh, *wl, *tqh, *tql, *ah, *al;
    float *att;
    cudaGetSymbolAddress((void**)&ph,  g_ph);   cudaGetSymbolAddress((void**)&pl,  g_pl);
    cudaGetSymbolAddress((void**)&qh,  g_qh);   cudaGetSymbolAddress((void**)&ql,  g_ql);
    cudaGetSymbolAddress((void**)&wh,  g_wh);   cudaGetSymbolAddress((void**)&wl,  g_wl);
    cudaGetSymbolAddress((void**)&tqh, g_tqh);  cudaGetSymbolAddress((void**)&tql, g_tql);
    cudaGetSymbolAddress((void**)&ah,  g_ah);   cudaGetSymbolAddress((void**)&al,  g_al);
    cudaGetSymbolAddress((void**)&att, g_att);

    cudaFuncSetAttribute(mm_bf16x3<true,  false, true,  false, true >,
                         cudaFuncAttributeMaxDynamicSharedMemorySize, SMEM_BYTES);
    cudaFuncSetAttribute(mm_bf16x3<false, false, false, false, false>,
                         cudaFuncAttributeMaxDynamicSharedMemorySize, SMEM_BYTES);
    cudaFuncSetAttribute(mm_bf16x3<false, true,  false, true,  false>,
                         cudaFuncAttributeMaxDynamicSharedMemorySize, SMEM_BYTES);

    const dim3 blk(256);
    const long long pn4 = (long long)BATCH * LP * HID / 4;

    // 0) split q and W only (proj_p split rides inside GEMM1)
    split_qw_kernel<<<dim3(2048, 2), 256>>>(proj_q, qh, ql,
                                            (long long)BATCH * LQ * HID / 4,
                                            W, wh, wl, (long long)HID * HID / 4);

    // 1) trans_q = proj_q @ W^T + b -> split bf16 [B*LQ, H]
    //    + 512 splitter CTAs converting proj_p in parallel (FUSE role CTAs)
    {
        const int nx = HID / TN;                       // 8
        const int ntiles = nx * ((BATCH * LQ) / TM);   // 2048
        mm_bf16x3<true, false, true, false, true>
            <<<ntiles + 512, blk, SMEM_BYTES>>>(
            qh, ql, wh, wl, bias, nullptr, tqh, tql, HID, HID, HID, HID,
            0, 0, 0, proj_p, ph, pl, pn4, nx, ntiles);
    }

    // 2) att[b] = proj_p[b] @ trans_q[b]^T  -> fp32 [LP, LQ]
    mm_bf16x3<false, false, false, false, false>
        <<<dim3(LQ / TN, LP / TM, BATCH), blk, SMEM_BYTES>>>(
        ph, pl, tqh, tql, nullptr, att, nullptr, nullptr, HID, HID, HID, LQ,
        (long long)LP * HID, (long long)LQ * HID, (long long)LP * LQ,
        nullptr, nullptr, nullptr, 0, 0, 0);

    // 3) softmax -> split bf16
    softmax_split<<<BATCH * LP, 256>>>(att, ah, al);

    // 4) out = relu(att_norm @ trans_q)  (bias folded; B via ldmatrix.trans)
    mm_bf16x3<false, true, false, true, false>
        <<<dim3(HID / TN, LP / TM, BATCH), blk, SMEM_BYTES>>>(
        ah, al, tqh, tql, nullptr, out, nullptr, nullptr, LQ, LQ, HID, HID,
        (long long)LP * LQ, (long long)LQ * HID, (long long)LP * HID,
        nullptr, nullptr, nullptr, 0, 0, 0);
}

// round 16
// speedup vs baseline: 1.3231x; 1.1816x over previous
#include <cuda_runtime.h>
#include <cuda_fp16.h>
#include <cstdint>

#define BATCH 16
#define LP    2048
#define LQ    2048
#define HID   1024

#define TM 128
#define TN 128
#define KS 32
#define TILE_B  (128 * 64)            // 8192 B per tile (both layouts)
#define STAGE_B (4 * TILE_B)          // 32768 B per stage (Ah, Al, Bh, Bl)
#define NSTAGE 3
#define SMEM_BYTES (NSTAGE * STAGE_B) // 98304 -> 2 CTAs/SM

typedef __half h16;

// ---------------- persistent scratch (allocation-free) ----------------
__device__ __align__(256) h16 g_ph [(size_t)BATCH * LP * HID];
__device__ __align__(256) h16 g_pl [(size_t)BATCH * LP * HID];
__device__ __align__(256) h16 g_qh [(size_t)BATCH * LQ * HID];
__device__ __align__(256) h16 g_ql [(size_t)BATCH * LQ * HID];
__device__ __align__(256) h16 g_wh [(size_t)HID * HID];
__device__ __align__(256) h16 g_wl [(size_t)HID * HID];
__device__ __align__(256) h16 g_tqh[(size_t)BATCH * LQ * HID];  // trans_q split
__device__ __align__(256) h16 g_tql[(size_t)BATCH * LQ * HID];
__device__ __align__(256) float g_att[(size_t)BATCH * LP * LQ];
__device__ __align__(256) h16 g_ah [(size_t)BATCH * LP * LQ];

// ------------------------- helpers -------------------------
__device__ __forceinline__ uint32_t smem_u32(const void* p) {
    uint32_t a;
    asm("{ .reg .u64 t; cvta.to.shared.u64 t, %1; cvt.u32.u64 %0, t; }"
        : "=r"(a) : "l"(p));
    return a;
}
// [128 rows x 64B] tile: swizzled byte offset of 16B chunk ch (0..3) of row r
__device__ __forceinline__ uint32_t sw_off(uint32_t r, uint32_t ch) {
    return ((r >> 1) << 7) | (((ch ^ ((r & 1) << 2) ^ ((r >> 1) & 3)) & 7) << 4);
}
// [32 rows x 256B] tile: swizzled byte offset of 16B chunk c (0..15) of row r
__device__ __forceinline__ uint32_t swt_off(uint32_t r, uint32_t c) {
    return (r << 8) | ((((c ^ r) & 7) | (c & 8)) << 4);
}
// packs: upper16 = fp16(hi), lower16 = fp16(lo)
__device__ __forceinline__ uint32_t cvth_pair(float hi, float lo) {
    uint32_t r;
    asm("cvt.rn.f16x2.f32 %0, %1, %2;" : "=r"(r) : "f"(hi), "f"(lo));
    return r;
}
__device__ __forceinline__ void ldsm4(uint32_t* r, uint32_t addr) {
    asm volatile("ldmatrix.sync.aligned.m8n8.x4.shared.b16 {%0,%1,%2,%3}, [%4];"
                 : "=r"(r[0]), "=r"(r[1]), "=r"(r[2]), "=r"(r[3]) : "r"(addr));
}
__device__ __forceinline__ void ldsm4t(uint32_t* r, uint32_t addr) {
    asm volatile("ldmatrix.sync.aligned.m8n8.x4.trans.shared.b16 {%0,%1,%2,%3}, [%4];"
                 : "=r"(r[0]), "=r"(r[1]), "=r"(r[2]), "=r"(r[3]) : "r"(addr));
}
__device__ __forceinline__ void mma16816(float* c, const uint32_t* a,
                                         uint32_t b0, uint32_t b1) {
    asm volatile(
        "mma.sync.aligned.m16n8k16.row.col.f32.f16.f16.f32 "
        "{%0,%1,%2,%3}, {%4,%5,%6,%7}, {%8,%9}, {%0,%1,%2,%3};"
        : "+f"(c[0]), "+f"(c[1]), "+f"(c[2]), "+f"(c[3])
        : "r"(a[0]), "r"(a[1]), "r"(a[2]), "r"(a[3]), "r"(b0), "r"(b1));
}
__device__ __forceinline__ void cpasync16(uint32_t saddr, const void* g) {
    asm volatile("cp.async.cg.shared.global [%0], [%1], 16;"
                 :: "r"(saddr), "l"(g) : "memory");
}
// split two floats -> (hiWord, loWord) packed fp16x2  (v0 -> lower half)
__device__ __forceinline__ void split2(float v0, float v1, uint32_t& h, uint32_t& l) {
    h = cvth_pair(v1, v0);
    float f0, f1;
    asm("{ .reg .b16 x, y;\n mov.b32 {x, y}, %2;\n"
        " cvt.f32.f16 %0, x;\n cvt.f32.f16 %1, y; }"
        : "=f"(f0), "=f"(f1) : "r"(h));
    l = cvth_pair(v1 - f1, v0 - f0);
}

// ---------------------------------------------------------------------------
// fp16-split HMMA GEMM: swizzled smem, 3-stage cp.async pipeline, one
// sync/stage, 2 CTAs/SM.
// PASS3=true : 3 passes (ah·bh + ah·bl + al·bh)  — full split precision.
// PASS3=false: 2 passes (ah·bh + ah·bl)          — A-lo tile never loaded.
// FUSE=true: 1-D grid; CTAs with bid >= ntiles run the proj_p split instead.
// BTR=false: B is [N,K] (k contiguous).  BTR=true: B is [K,N], ldmatrix.trans.
// C[M,N] = A[M,K] * B^T (+bias)(+ReLU)
// ---------------------------------------------------------------------------
template <bool BIAS, bool RELU, bool OSPLIT, bool BTR, bool FUSE, bool PASS3>
__global__ void __launch_bounds__(256, 2)
mm_h16(const h16* __restrict__ Ah, const h16* __restrict__ Al,
       const h16* __restrict__ Bh, const h16* __restrict__ Bl,
       const float* __restrict__ bias,
       float* __restrict__ Cf, h16* __restrict__ Chi, h16* __restrict__ Clo,
       int K, int lda, int ldb, int ldc,
       long long sA, long long sB, long long sC,
       const float* __restrict__ Pin, h16* __restrict__ Phi,
       h16* __restrict__ Plo, long long pn4, int nx, int ntiles)
{
    extern __shared__ uint8_t sm[];
    const uint32_t smem = smem_u32(sm);
    const int tid  = threadIdx.x;
    const int lane = tid & 31;
    const int wid  = tid >> 5;
    const int wm   = wid & 3;
    const int wn   = wid >> 2;

    int tx, ty, z;
    if (FUSE) {
        const int bid = (int)blockIdx.x;
        if (bid >= ntiles) {
            // -------- splitter role: fp32 proj_p -> fp16 hi/lo --------
            const long long stride =
                (long long)((int)gridDim.x - ntiles) * blockDim.x;
            for (long long i = (long long)(bid - ntiles) * blockDim.x + tid;
                 i < pn4; i += stride) {
                float4 v = ((const float4*)Pin)[i];
                uint32_t h01, l01, h23, l23;
                split2(v.x, v.y, h01, l01);
                split2(v.z, v.w, h23, l23);
                ((uint2*)Phi)[i] = make_uint2(h01, h23);
                ((uint2*)Plo)[i] = make_uint2(l01, l23);
            }
            return;
        }
        ty = bid / nx;
        tx = bid - ty * nx;
        z  = 0;
    } else {
        tx = (int)blockIdx.x; ty = (int)blockIdx.y; z = (int)blockIdx.z;
    }

    const long long zz = z;
    Ah += sA * zz;  if (PASS3) Al += sA * zz;
    Bh += sB * zz;  Bl += sB * zz;
    if (OSPLIT) { Chi += sC * zz; Clo += sC * zz; }
    else        { Cf  += sC * zz; }

    const int m0 = ty * TM;
    const int n0 = tx * TN;

    // ---- cp.async mappings ----
    const int arow = tid >> 2;
    const int ach  = tid & 3;
    const h16* gAh = Ah + (long long)(m0 + arow) * lda + ach * 8;
    const h16* gAl = PASS3 ? (Al + (long long)(m0 + arow) * lda + ach * 8) : nullptr;
    const uint32_t aso0 = sw_off((uint32_t)arow,      (uint32_t)ach);
    const uint32_t aso1 = sw_off((uint32_t)arow + 64, (uint32_t)ach);

    const h16 *gBh, *gBl;
    uint32_t bso0, bso1;
    long long bstep1;
    if (BTR) {
        const int brow = tid >> 4;          // 0..15 (second chunk: +16)
        const int bc   = tid & 15;
        gBh = Bh + (long long)brow * ldb + n0 + bc * 8;
        gBl = Bl + (long long)brow * ldb + n0 + bc * 8;
        bso0 = swt_off((uint32_t)brow,      (uint32_t)bc);
        bso1 = swt_off((uint32_t)brow + 16, (uint32_t)bc);
        bstep1 = 16LL * ldb;
    } else {
        const int brow = tid >> 2;
        const int bch  = tid & 3;
        gBh = Bh + (long long)(n0 + brow) * ldb + bch * 8;
        gBl = Bl + (long long)(n0 + brow) * ldb + bch * 8;
        bso0 = sw_off((uint32_t)brow,      (uint32_t)bch);
        bso1 = sw_off((uint32_t)brow + 64, (uint32_t)bch);
        bstep1 = 64LL * ldb;
    }

    const int ns = K / KS;

    auto issue = [&](int s) {
        if (s < ns) {
            const uint32_t b = smem + (uint32_t)(s % NSTAGE) * STAGE_B;
            const long long ko = (long long)s * KS;
            cpasync16(b + aso0,          gAh + ko);
            cpasync16(b + aso1,          gAh + ko + 64LL * lda);
            if (PASS3) {
                cpasync16(b + TILE_B + aso0, gAl + ko);
                cpasync16(b + TILE_B + aso1, gAl + ko + 64LL * lda);
            }
            const long long bko = BTR ? ko * ldb : ko;
            cpasync16(b + 2 * TILE_B + bso0, gBh + bko);
            cpasync16(b + 2 * TILE_B + bso1, gBh + bko + bstep1);
            cpasync16(b + 3 * TILE_B + bso0, gBl + bko);
            cpasync16(b + 3 * TILE_B + bso1, gBl + bko + bstep1);
        }
        asm volatile("cp.async.commit_group;" ::: "memory");
    };

    issue(0); issue(1);

    // fragment coordinates
    const uint32_t a_r  = (uint32_t)(wm * 32 + (lane & 15));
    const uint32_t a_ch = (uint32_t)((lane >> 4) & 1);
    const uint32_t b_r  = (uint32_t)(wn * 64 + (lane & 7) + ((lane & 16) >> 1)); // !BTR
    const uint32_t b_ch = (uint32_t)((lane >> 3) & 1);                           // !BTR
    const uint32_t bt_r = (uint32_t)(lane & 15);                                 // BTR: k row
    const uint32_t bt_c = (uint32_t)(wn * 8 + (lane >> 4));                      // BTR: chunk

    float acc[2][8][4];
    #pragma unroll
    for (int i = 0; i < 2; i++)
        #pragma unroll
        for (int j = 0; j < 8; j++)
            #pragma unroll
            for (int r = 0; r < 4; r++) acc[i][j][r] = 0.f;

    for (int s = 0; s < ns; s++) {
        asm volatile("cp.async.wait_group 1;" ::: "memory");
        __syncthreads();
        issue(s + 2);   // (s+2)%3 == (s-1)%3: all warps finished it at stage s-1

        const uint32_t base = smem + (uint32_t)(s % NSTAGE) * STAGE_B;
        #pragma unroll
        for (int kk2 = 0; kk2 < 2; kk2++) {
            uint32_t ah[2][4], al[2][4];
            #pragma unroll
            for (int t = 0; t < 2; t++) {
                const uint32_t o = sw_off(a_r + t * 16, 2 * kk2 + a_ch);
                ldsm4(ah[t], base + o);
                if (PASS3) ldsm4(al[t], base + TILE_B + o);
            }
            #pragma unroll
            for (int tb = 0; tb < 4; tb++) {
                uint32_t bh[4], bl[4];
                if (BTR) {
                    const uint32_t o = swt_off(kk2 * 16 + bt_r, bt_c + tb * 2);
                    ldsm4t(bh, base + 2 * TILE_B + o);
                    ldsm4t(bl, base + 3 * TILE_B + o);
                } else {
                    const uint32_t o = sw_off(b_r + tb * 16, 2 * kk2 + b_ch);
                    ldsm4(bh, base + 2 * TILE_B + o);
                    ldsm4(bl, base + 3 * TILE_B + o);
                }
                #pragma unroll
                for (int mi = 0; mi < 2; mi++) {
                    mma16816(acc[mi][2 * tb],     ah[mi], bh[0], bh[1]);
                    mma16816(acc[mi][2 * tb],     ah[mi], bl[0], bl[1]);
                    if (PASS3)
                        mma16816(acc[mi][2 * tb], al[mi], bh[0], bh[1]);
                    mma16816(acc[mi][2 * tb + 1], ah[mi], bh[2], bh[3]);
                    mma16816(acc[mi][2 * tb + 1], ah[mi], bl[2], bl[3]);
                    if (PASS3)
                        mma16816(acc[mi][2 * tb + 1], al[mi], bh[2], bh[3]);
                }
            }
        }
    }

    // ---- epilogue ----
    const int g  = lane >> 2;
    const int t4 = lane & 3;
    #pragma unroll
    for (int mi = 0; mi < 2; mi++) {
        #pragma unroll
        for (int ni = 0; ni < 8; ni++) {
            const int row = m0 + wm * 32 + mi * 16 + g;
            const int col = n0 + wn * 64 + ni * 8 + t4 * 2;
            float* c = acc[mi][ni];
            float b0 = 0.f, b1 = 0.f;
            if (BIAS) { b0 = __ldg(&bias[col]); b1 = __ldg(&bias[col + 1]); }
            float v00 = c[0] + b0, v01 = c[1] + b1;
            float v10 = c[2] + b0, v11 = c[3] + b1;
            if (RELU) {
                v00 = fmaxf(v00, 0.f); v01 = fmaxf(v01, 0.f);
                v10 = fmaxf(v10, 0.f); v11 = fmaxf(v11, 0.f);
            }
            if (OSPLIT) {
                uint32_t h, l;
                split2(v00, v01, h, l);
                ((uint32_t*)Chi)[((long long)row * ldc + col) >> 1] = h;
                ((uint32_t*)Clo)[((long long)row * ldc + col) >> 1] = l;
                split2(v10, v11, h, l);
                ((uint32_t*)Chi)[((long long)(row + 8) * ldc + col) >> 1] = h;
                ((uint32_t*)Clo)[((long long)(row + 8) * ldc + col) >> 1] = l;
            } else {
                *(float2*)&Cf[(long long)row * ldc + col]       = make_float2(v00, v01);
                *(float2*)&Cf[(long long)(row + 8) * ldc + col] = make_float2(v10, v11);
            }
        }
    }
}

// ---------------------------------------------------------------------------
// Elementwise split: fp32 -> fp16 hi/lo, two tensors in one launch (q, W)
// ---------------------------------------------------------------------------
__global__ __launch_bounds__(256)
void split_qw_kernel(const float* __restrict__ in0, h16* __restrict__ hi0,
                     h16* __restrict__ lo0, long long n4q,
                     const float* __restrict__ in1, h16* __restrict__ hi1,
                     h16* __restrict__ lo1, long long n4w)
{
    const float* in = blockIdx.y ? in1 : in0;
    h16* hi = blockIdx.y ? hi1 : hi0;
    h16* lo = blockIdx.y ? lo1 : lo0;
    const long long n4 = blockIdx.y ? n4w : n4q;
    const long long stride = (long long)gridDim.x * blockDim.x;
    for (long long i = (long long)blockIdx.x * blockDim.x + threadIdx.x;
         i < n4; i += stride) {
        float4 v = ((const float4*)in)[i];
        uint32_t h01, l01, h23, l23;
        split2(v.x, v.y, h01, l01);
        split2(v.z, v.w, h23, l23);
        ((uint2*)hi)[i] = make_uint2(h01, h23);
        ((uint2*)lo)[i] = make_uint2(l01, l23);
    }
}

// ---------------------------------------------------------------------------
// Row softmax (2048) reading fp32, writing fp16 hi ONLY (GEMM4 is 2-pass).
// ---------------------------------------------------------------------------
__global__ __launch_bounds__(256)
void softmax_h16(const float* __restrict__ att, h16* __restrict__ oh)
{
    const float* row = att + (long long)blockIdx.x * 2048;
    uint32_t* oh32 = (uint32_t*)oh + (long long)blockIdx.x * 1024;
    const int tid = threadIdx.x;
    const int wid = tid >> 5, lane = tid & 31;

    float2 v[4];
    float m = -3.4e38f;
    #pragma unroll
    for (int i = 0; i < 4; i++) {
        v[i] = ((const float2*)row)[tid + 256 * i];
        m = fmaxf(m, fmaxf(v[i].x, v[i].y));
    }
    #pragma unroll
    for (int o = 16; o > 0; o >>= 1) m = fmaxf(m, __shfl_xor_sync(0xffffffffu, m, o));

    __shared__ float red[8];
    __shared__ float sval;
    if (lane == 0) red[wid] = m;
    __syncthreads();
    if (tid == 0) {
        float t = red[0];
        #pragma unroll
        for (int w = 1; w < 8; w++) t = fmaxf(t, red[w]);
        sval = t;
    }
    __syncthreads();
    m = sval;

    float s = 0.f;
    #pragma unroll
    for (int i = 0; i < 4; i++) {
        v[i].x = expf(v[i].x - m);
        v[i].y = expf(v[i].y - m);
        s += v[i].x + v[i].y;
    }
    #pragma unroll
    for (int o = 16; o > 0; o >>= 1) s += __shfl_xor_sync(0xffffffffu, s, o);
    __syncthreads();
    if (lane == 0) red[wid] = s;
    __syncthreads();
    if (tid == 0) {
        float t = 0.f;
        #pragma unroll
        for (int w = 0; w < 8; w++) t += red[w];
        sval = 1.0f / t;
    }
    __syncthreads();
    const float inv = sval;
    #pragma unroll
    for (int i = 0; i < 4; i++) {
        oh32[tid + 256 * i] = cvth_pair(v[i].y * inv, v[i].x * inv);
    }
}

// ---------------------------------------------------------------------------
extern "C" void kernel_launch(void* const* d_in, const int* in_sizes, int n_in,
                              void* d_out, int out_size)
{
    const float* proj_p = (const float*)d_in[0];   // [B, LP, H]
    const float* proj_q = (const float*)d_in[1];   // [B, LQ, H]
    const float* W      = (const float*)d_in[2];   // [H, H]
    const float* bias   = (const float*)d_in[3];   // [H]
    float* out = (float*)d_out;                    // [B, LP, H]

    h16 *ph, *pl, *qh, *ql, *wh, *wl, *tqh, *tql, *ah;
    float *att;
    cudaGetSymbolAddress((void**)&ph,  g_ph);   cudaGetSymbolAddress((void**)&pl,  g_pl);
    cudaGetSymbolAddress((void**)&qh,  g_qh);   cudaGetSymbolAddress((void**)&ql,  g_ql);
    cudaGetSymbolAddress((void**)&wh,  g_wh);   cudaGetSymbolAddress((void**)&wl,  g_wl);
    cudaGetSymbolAddress((void**)&tqh, g_tqh);  cudaGetSymbolAddress((void**)&tql, g_tql);
    cudaGetSymbolAddress((void**)&ah,  g_ah);
    cudaGetSymbolAddress((void**)&att, g_att);

    cudaFuncSetAttribute(mm_h16<true,  false, true,  false, true,  true >,
                         cudaFuncAttributeMaxDynamicSharedMemorySize, SMEM_BYTES);
    cudaFuncSetAttribute(mm_h16<false, false, false, false, false, true >,
                         cudaFuncAttributeMaxDynamicSharedMemorySize, SMEM_BYTES);
    cudaFuncSetAttribute(mm_h16<false, true,  false, true,  false, false>,
                         cudaFuncAttributeMaxDynamicSharedMemorySize, SMEM_BYTES);

    const dim3 blk(256);
    const long long pn4 = (long long)BATCH * LP * HID / 4;

    // 0) split q and W only (proj_p split rides inside GEMM1)
    split_qw_kernel<<<dim3(2048, 2), 256>>>(proj_q, qh, ql,
                                            (long long)BATCH * LQ * HID / 4,
                                            W, wh, wl, (long long)HID * HID / 4);

    // 1) trans_q = proj_q @ W^T + b -> split fp16 [B*LQ, H]; 3-pass
    //    + 512 splitter CTAs converting proj_p in parallel (FUSE role CTAs)
    {
        const int nx = HID / TN;                       // 8
        const int ntiles = nx * ((BATCH * LQ) / TM);   // 2048
        mm_h16<true, false, true, false, true, true>
            <<<ntiles + 512, blk, SMEM_BYTES>>>(
            qh, ql, wh, wl, bias, nullptr, tqh, tql, HID, HID, HID, HID,
            0, 0, 0, proj_p, ph, pl, pn4, nx, ntiles);
    }

    // 2) att[b] = proj_p[b] @ trans_q[b]^T  -> fp32 [LP, LQ]; 3-pass
    mm_h16<false, false, false, false, false, true>
        <<<dim3(LQ / TN, LP / TM, BATCH), blk, SMEM_BYTES>>>(
        ph, pl, tqh, tql, nullptr, att, nullptr, nullptr, HID, HID, HID, LQ,
        (long long)LP * HID, (long long)LQ * HID, (long long)LP * LQ,
        nullptr, nullptr, nullptr, 0, 0, 0);

    // 3) softmax -> fp16 hi only
    softmax_h16<<<BATCH * LP, 256>>>(att, ah);

    // 4) out = relu(att_norm @ trans_q)  — 2-pass fp16 (A-lo dropped: att rows
    //    sum to 1, error ~2^-12; bias folded; B via ldmatrix.trans)
    mm_h16<false, true, false, true, false, false>
        <<<dim3(HID / TN, LP / TM, BATCH), blk, SMEM_BYTES>>>(
        ah, nullptr, tqh, tql, nullptr, out, nullptr, nullptr, LQ, LQ, HID, HID,
        (long long)LP * LQ, (long long)LQ * HID, (long long)LP * HID,
        nullptr, nullptr, nullptr, 0, 0, 0);
}

// round 17
// speedup vs baseline: 1.4716x; 1.1122x over previous
#include <cuda_runtime.h>
#include <cuda_fp16.h>
#include <cstdint>

#define BATCH 16
#define LP    2048
#define LQ    2048
#define HID   1024

#define TM 128
#define TN 128
#define KS 32
#define TILE_B  (128 * 64)            // 8192 B per tile (both layouts)
#define STAGE_B (4 * TILE_B)          // 32768 B per stage (Ah, Al, Bh, Bl)
#define NSTAGE 3
#define SMEM_BYTES (NSTAGE * STAGE_B) // 98304 -> 2 CTAs/SM

typedef __half h16;

// ---------------- persistent scratch (allocation-free) ----------------
__device__ __align__(256) h16 g_ph [(size_t)BATCH * LP * HID];
__device__ __align__(256) h16 g_pl [(size_t)BATCH * LP * HID];
__device__ __align__(256) h16 g_qh [(size_t)BATCH * LQ * HID];
__device__ __align__(256) h16 g_ql [(size_t)BATCH * LQ * HID];
__device__ __align__(256) h16 g_wh [(size_t)HID * HID];
__device__ __align__(256) h16 g_wl [(size_t)HID * HID];
__device__ __align__(256) h16 g_tqh[(size_t)BATCH * LQ * HID];  // trans_q split
__device__ __align__(256) h16 g_tql[(size_t)BATCH * LQ * HID];
__device__ __align__(256) float g_att[(size_t)BATCH * LP * LQ];
__device__ __align__(256) h16 g_ah [(size_t)BATCH * LP * LQ];

// ------------------------- helpers -------------------------
__device__ __forceinline__ uint32_t smem_u32(const void* p) {
    uint32_t a;
    asm("{ .reg .u64 t; cvta.to.shared.u64 t, %1; cvt.u32.u64 %0, t; }"
        : "=r"(a) : "l"(p));
    return a;
}
// [128 rows x 64B] tile: swizzled byte offset of 16B chunk ch (0..3) of row r
__device__ __forceinline__ uint32_t sw_off(uint32_t r, uint32_t ch) {
    return ((r >> 1) << 7) | (((ch ^ ((r & 1) << 2) ^ ((r >> 1) & 3)) & 7) << 4);
}
// [32 rows x 256B] tile: swizzled byte offset of 16B chunk c (0..15) of row r
__device__ __forceinline__ uint32_t swt_off(uint32_t r, uint32_t c) {
    return (r << 8) | ((((c ^ r) & 7) | (c & 8)) << 4);
}
// packs: upper16 = fp16(hi), lower16 = fp16(lo)
__device__ __forceinline__ uint32_t cvth_pair(float hi, float lo) {
    uint32_t r;
    asm("cvt.rn.f16x2.f32 %0, %1, %2;" : "=r"(r) : "f"(hi), "f"(lo));
    return r;
}
__device__ __forceinline__ void ldsm4(uint32_t* r, uint32_t addr) {
    asm volatile("ldmatrix.sync.aligned.m8n8.x4.shared.b16 {%0,%1,%2,%3}, [%4];"
                 : "=r"(r[0]), "=r"(r[1]), "=r"(r[2]), "=r"(r[3]) : "r"(addr));
}
__device__ __forceinline__ void ldsm4t(uint32_t* r, uint32_t addr) {
    asm volatile("ldmatrix.sync.aligned.m8n8.x4.trans.shared.b16 {%0,%1,%2,%3}, [%4];"
                 : "=r"(r[0]), "=r"(r[1]), "=r"(r[2]), "=r"(r[3]) : "r"(addr));
}
__device__ __forceinline__ void mma16816(float* c, const uint32_t* a,
                                         uint32_t b0, uint32_t b1) {
    asm volatile(
        "mma.sync.aligned.m16n8k16.row.col.f32.f16.f16.f32 "
        "{%0,%1,%2,%3}, {%4,%5,%6,%7}, {%8,%9}, {%0,%1,%2,%3};"
        : "+f"(c[0]), "+f"(c[1]), "+f"(c[2]), "+f"(c[3])
        : "r"(a[0]), "r"(a[1]), "r"(a[2]), "r"(a[3]), "r"(b0), "r"(b1));
}
__device__ __forceinline__ void cpasync16(uint32_t saddr, const void* g) {
    asm volatile("cp.async.cg.shared.global [%0], [%1], 16;"
                 :: "r"(saddr), "l"(g) : "memory");
}
// split two floats -> (hiWord, loWord) packed fp16x2  (v0 -> lower half)
__device__ __forceinline__ void split2(float v0, float v1, uint32_t& h, uint32_t& l) {
    h = cvth_pair(v1, v0);
    float f0, f1;
    asm("{ .reg .b16 x, y;\n mov.b32 {x, y}, %2;\n"
        " cvt.f32.f16 %0, x;\n cvt.f32.f16 %1, y; }"
        : "=f"(f0), "=f"(f1) : "r"(h));
    l = cvth_pair(v1 - f1, v0 - f0);
}

// ---------------------------------------------------------------------------
// fp16-split HMMA GEMM: swizzled smem, 3-stage cp.async pipeline, one
// sync/stage, 2 CTAs/SM.
// PASSES=3: ah·bh + ah·bl + al·bh (full split precision)
// PASSES=2: ah·bh + ah·bl         (A-lo tile never loaded)
// PASSES=1: ah·bh                 (plain fp16: A-lo and B-lo never loaded)
// FUSE=true: 1-D grid; CTAs with bid >= ntiles run the proj_p split instead.
// BTR=false: B is [N,K] (k contiguous).  BTR=true: B is [K,N], ldmatrix.trans.
// C[M,N] = A[M,K] * B^T (+bias)(+ReLU)
// ---------------------------------------------------------------------------
template <bool BIAS, bool RELU, bool OSPLIT, bool BTR, bool FUSE, int PASSES>
__global__ void __launch_bounds__(256, 2)
mm_h16(const h16* __restrict__ Ah, const h16* __restrict__ Al,
       const h16* __restrict__ Bh, const h16* __restrict__ Bl,
       const float* __restrict__ bias,
       float* __restrict__ Cf, h16* __restrict__ Chi, h16* __restrict__ Clo,
       int K, int lda, int ldb, int ldc,
       long long sA, long long sB, long long sC,
       const float* __restrict__ Pin, h16* __restrict__ Phi,
       h16* __restrict__ Plo, long long pn4, int nx, int ntiles)
{
    extern __shared__ uint8_t sm[];
    const uint32_t smem = smem_u32(sm);
    const int tid  = threadIdx.x;
    const int lane = tid & 31;
    const int wid  = tid >> 5;
    const int wm   = wid & 3;
    const int wn   = wid >> 2;

    int tx, ty, z;
    if (FUSE) {
        const int bid = (int)blockIdx.x;
        if (bid >= ntiles) {
            // -------- splitter role: fp32 proj_p -> fp16 hi/lo --------
            const long long stride =
                (long long)((int)gridDim.x - ntiles) * blockDim.x;
            for (long long i = (long long)(bid - ntiles) * blockDim.x + tid;
                 i < pn4; i += stride) {
                float4 v = ((const float4*)Pin)[i];
                uint32_t h01, l01, h23, l23;
                split2(v.x, v.y, h01, l01);
                split2(v.z, v.w, h23, l23);
                ((uint2*)Phi)[i] = make_uint2(h01, h23);
                ((uint2*)Plo)[i] = make_uint2(l01, l23);
            }
            return;
        }
        ty = bid / nx;
        tx = bid - ty * nx;
        z  = 0;
    } else {
        tx = (int)blockIdx.x; ty = (int)blockIdx.y; z = (int)blockIdx.z;
    }

    const long long zz = z;
    Ah += sA * zz;  if (PASSES >= 3) Al += sA * zz;
    Bh += sB * zz;  if (PASSES >= 2) Bl += sB * zz;
    if (OSPLIT) { Chi += sC * zz; Clo += sC * zz; }
    else        { Cf  += sC * zz; }

    const int m0 = ty * TM;
    const int n0 = tx * TN;

    // ---- cp.async mappings ----
    const int arow = tid >> 2;
    const int ach  = tid & 3;
    const h16* gAh = Ah + (long long)(m0 + arow) * lda + ach * 8;
    const h16* gAl = (PASSES >= 3) ? (Al + (long long)(m0 + arow) * lda + ach * 8)
                                   : nullptr;
    const uint32_t aso0 = sw_off((uint32_t)arow,      (uint32_t)ach);
    const uint32_t aso1 = sw_off((uint32_t)arow + 64, (uint32_t)ach);

    const h16 *gBh, *gBl = nullptr;
    uint32_t bso0, bso1;
    long long bstep1;
    if (BTR) {
        const int brow = tid >> 4;          // 0..15 (second chunk: +16)
        const int bc   = tid & 15;
        gBh = Bh + (long long)brow * ldb + n0 + bc * 8;
        if (PASSES >= 2) gBl = Bl + (long long)brow * ldb + n0 + bc * 8;
        bso0 = swt_off((uint32_t)brow,      (uint32_t)bc);
        bso1 = swt_off((uint32_t)brow + 16, (uint32_t)bc);
        bstep1 = 16LL * ldb;
    } else {
        const int brow = tid >> 2;
        const int bch  = tid & 3;
        gBh = Bh + (long long)(n0 + brow) * ldb + bch * 8;
        if (PASSES >= 2) gBl = Bl + (long long)(n0 + brow) * ldb + bch * 8;
        bso0 = sw_off((uint32_t)brow,      (uint32_t)bch);
        bso1 = sw_off((uint32_t)brow + 64, (uint32_t)bch);
        bstep1 = 64LL * ldb;
    }

    const int ns = K / KS;

    auto issue = [&](int s) {
        if (s < ns) {
            const uint32_t b = smem + (uint32_t)(s % NSTAGE) * STAGE_B;
            const long long ko = (long long)s * KS;
            cpasync16(b + aso0,          gAh + ko);
            cpasync16(b + aso1,          gAh + ko + 64LL * lda);
            if (PASSES >= 3) {
                cpasync16(b + TILE_B + aso0, gAl + ko);
                cpasync16(b + TILE_B + aso1, gAl + ko + 64LL * lda);
            }
            const long long bko = BTR ? ko * ldb : ko;
            cpasync16(b + 2 * TILE_B + bso0, gBh + bko);
            cpasync16(b + 2 * TILE_B + bso1, gBh + bko + bstep1);
            if (PASSES >= 2) {
                cpasync16(b + 3 * TILE_B + bso0, gBl + bko);
                cpasync16(b + 3 * TILE_B + bso1, gBl + bko + bstep1);
            }
        }
        asm volatile("cp.async.commit_group;" ::: "memory");
    };

    issue(0); issue(1);

    // fragment coordinates
    const uint32_t a_r  = (uint32_t)(wm * 32 + (lane & 15));
    const uint32_t a_ch = (uint32_t)((lane >> 4) & 1);
    const uint32_t b_r  = (uint32_t)(wn * 64 + (lane & 7) + ((lane & 16) >> 1)); // !BTR
    const uint32_t b_ch = (uint32_t)((lane >> 3) & 1);                           // !BTR
    const uint32_t bt_r = (uint32_t)(lane & 15);                                 // BTR: k row
    const uint32_t bt_c = (uint32_t)(wn * 8 + (lane >> 4));                      // BTR: chunk

    float acc[2][8][4];
    #pragma unroll
    for (int i = 0; i < 2; i++)
        #pragma unroll
        for (int j = 0; j < 8; j++)
            #pragma unroll
            for (int r = 0; r < 4; r++) acc[i][j][r] = 0.f;

    for (int s = 0; s < ns; s++) {
        asm volatile("cp.async.wait_group 1;" ::: "memory");
        __syncthreads();
        issue(s + 2);   // (s+2)%3 == (s-1)%3: all warps finished it at stage s-1

        const uint32_t base = smem + (uint32_t)(s % NSTAGE) * STAGE_B;
        #pragma unroll
        for (int kk2 = 0; kk2 < 2; kk2++) {
            uint32_t ah[2][4], al[2][4];
            #pragma unroll
            for (int t = 0; t < 2; t++) {
                const uint32_t o = sw_off(a_r + t * 16, 2 * kk2 + a_ch);
                ldsm4(ah[t], base + o);
                if (PASSES >= 3) ldsm4(al[t], base + TILE_B + o);
            }
            #pragma unroll
            for (int tb = 0; tb < 4; tb++) {
                uint32_t bh[4], bl[4];
                if (BTR) {
                    const uint32_t o = swt_off(kk2 * 16 + bt_r, bt_c + tb * 2);
                    ldsm4t(bh, base + 2 * TILE_B + o);
                    if (PASSES >= 2) ldsm4t(bl, base + 3 * TILE_B + o);
                } else {
                    const uint32_t o = sw_off(b_r + tb * 16, 2 * kk2 + b_ch);
                    ldsm4(bh, base + 2 * TILE_B + o);
                    if (PASSES >= 2) ldsm4(bl, base + 3 * TILE_B + o);
                }
                #pragma unroll
                for (int mi = 0; mi < 2; mi++) {
                    mma16816(acc[mi][2 * tb],     ah[mi], bh[0], bh[1]);
                    if (PASSES >= 2)
                        mma16816(acc[mi][2 * tb], ah[mi], bl[0], bl[1]);
                    if (PASSES >= 3)
                        mma16816(acc[mi][2 * tb], al[mi], bh[0], bh[1]);
                    mma16816(acc[mi][2 * tb + 1], ah[mi], bh[2], bh[3]);
                    if (PASSES >= 2)
                        mma16816(acc[mi][2 * tb + 1], ah[mi], bl[2], bl[3]);
                    if (PASSES >= 3)
                        mma16816(acc[mi][2 * tb + 1], al[mi], bh[2], bh[3]);
                }
            }
        }
    }

    // ---- epilogue ----
    const int g  = lane >> 2;
    const int t4 = lane & 3;
    #pragma unroll
    for (int mi = 0; mi < 2; mi++) {
        #pragma unroll
        for (int ni = 0; ni < 8; ni++) {
            const int row = m0 + wm * 32 + mi * 16 + g;
            const int col = n0 + wn * 64 + ni * 8 + t4 * 2;
            float* c = acc[mi][ni];
            float b0 = 0.f, b1 = 0.f;
            if (BIAS) { b0 = __ldg(&bias[col]); b1 = __ldg(&bias[col + 1]); }
            float v00 = c[0] + b0, v01 = c[1] + b1;
            float v10 = c[2] + b0, v11 = c[3] + b1;
            if (RELU) {
                v00 = fmaxf(v00, 0.f); v01 = fmaxf(v01, 0.f);
                v10 = fmaxf(v10, 0.f); v11 = fmaxf(v11, 0.f);
            }
            if (OSPLIT) {
                uint32_t h, l;
                split2(v00, v01, h, l);
                ((uint32_t*)Chi)[((long long)row * ldc + col) >> 1] = h;
                ((uint32_t*)Clo)[((long long)row * ldc + col) >> 1] = l;
                split2(v10, v11, h, l);
                ((uint32_t*)Chi)[((long long)(row + 8) * ldc + col) >> 1] = h;
                ((uint32_t*)Clo)[((long long)(row + 8) * ldc + col) >> 1] = l;
            } else {
                *(float2*)&Cf[(long long)row * ldc + col]       = make_float2(v00, v01);
                *(float2*)&Cf[(long long)(row + 8) * ldc + col] = make_float2(v10, v11);
            }
        }
    }
}

// ---------------------------------------------------------------------------
// Elementwise split: fp32 -> fp16 hi/lo, two tensors in one launch (q, W)
// ---------------------------------------------------------------------------
__global__ __launch_bounds__(256)
void split_qw_kernel(const float* __restrict__ in0, h16* __restrict__ hi0,
                     h16* __restrict__ lo0, long long n4q,
                     const float* __restrict__ in1, h16* __restrict__ hi1,
                     h16* __restrict__ lo1, long long n4w)
{
    const float* in = blockIdx.y ? in1 : in0;
    h16* hi = blockIdx.y ? hi1 : hi0;
    h16* lo = blockIdx.y ? lo1 : lo0;
    const long long n4 = blockIdx.y ? n4w : n4q;
    const long long stride = (long long)gridDim.x * blockDim.x;
    for (long long i = (long long)blockIdx.x * blockDim.x + threadIdx.x;
         i < n4; i += stride) {
        float4 v = ((const float4*)in)[i];
        uint32_t h01, l01, h23, l23;
        split2(v.x, v.y, h01, l01);
        split2(v.z, v.w, h23, l23);
        ((uint2*)hi)[i] = make_uint2(h01, h23);
        ((uint2*)lo)[i] = make_uint2(l01, l23);
    }
}

// ---------------------------------------------------------------------------
// Row softmax (2048) reading fp32, writing fp16 hi ONLY (GEMM4 is 1-pass).
// ---------------------------------------------------------------------------
__global__ __launch_bounds__(256)
void softmax_h16(const float* __restrict__ att, h16* __restrict__ oh)
{
    const float* row = att + (long long)blockIdx.x * 2048;
    uint32_t* oh32 = (uint32_t*)oh + (long long)blockIdx.x * 1024;
    const int tid = threadIdx.x;
    const int wid = tid >> 5, lane = tid & 31;

    float2 v[4];
    float m = -3.4e38f;
    #pragma unroll
    for (int i = 0; i < 4; i++) {
        v[i] = ((const float2*)row)[tid + 256 * i];
        m = fmaxf(m, fmaxf(v[i].x, v[i].y));
    }
    #pragma unroll
    for (int o = 16; o > 0; o >>= 1) m = fmaxf(m, __shfl_xor_sync(0xffffffffu, m, o));

    __shared__ float red[8];
    __shared__ float sval;
    if (lane == 0) red[wid] = m;
    __syncthreads();
    if (tid == 0) {
        float t = red[0];
        #pragma unroll
        for (int w = 1; w < 8; w++) t = fmaxf(t, red[w]);
        sval = t;
    }
    __syncthreads();
    m = sval;

    float s = 0.f;
    #pragma unroll
    for (int i = 0; i < 4; i++) {
        v[i].x = expf(v[i].x - m);
        v[i].y = expf(v[i].y - m);
        s += v[i].x + v[i].y;
    }
    #pragma unroll
    for (int o = 16; o > 0; o >>= 1) s += __shfl_xor_sync(0xffffffffu, s, o);
    __syncthreads();
    if (lane == 0) red[wid] = s;
    __syncthreads();
    if (tid == 0) {
        float t = 0.f;
        #pragma unroll
        for (int w = 0; w < 8; w++) t += red[w];
        sval = 1.0f / t;
    }
    __syncthreads();
    const float inv = sval;
    #pragma unroll
    for (int i = 0; i < 4; i++) {
        oh32[tid + 256 * i] = cvth_pair(v[i].y * inv, v[i].x * inv);
    }
}

// ---------------------------------------------------------------------------
extern "C" void kernel_launch(void* const* d_in, const int* in_sizes, int n_in,
                              void* d_out, int out_size)
{
    const float* proj_p = (const float*)d_in[0];   // [B, LP, H]
    const float* proj_q = (const float*)d_in[1];   // [B, LQ, H]
    const float* W      = (const float*)d_in[2];   // [H, H]
    const float* bias   = (const float*)d_in[3];   // [H]
    float* out = (float*)d_out;                    // [B, LP, H]

    h16 *ph, *pl, *qh, *ql, *wh, *wl, *tqh, *tql, *ah;
    float *att;
    cudaGetSymbolAddress((void**)&ph,  g_ph);   cudaGetSymbolAddress((void**)&pl,  g_pl);
    cudaGetSymbolAddress((void**)&qh,  g_qh);   cudaGetSymbolAddress((void**)&ql,  g_ql);
    cudaGetSymbolAddress((void**)&wh,  g_wh);   cudaGetSymbolAddress((void**)&wl,  g_wl);
    cudaGetSymbolAddress((void**)&tqh, g_tqh);  cudaGetSymbolAddress((void**)&tql, g_tql);
    cudaGetSymbolAddress((void**)&ah,  g_ah);
    cudaGetSymbolAddress((void**)&att, g_att);

    cudaFuncSetAttribute(mm_h16<true,  false, true,  false, true,  3>,
                         cudaFuncAttributeMaxDynamicSharedMemorySize, SMEM_BYTES);
    cudaFuncSetAttribute(mm_h16<false, false, false, false, false, 3>,
                         cudaFuncAttributeMaxDynamicSharedMemorySize, SMEM_BYTES);
    cudaFuncSetAttribute(mm_h16<false, true,  false, true,  false, 1>,
                         cudaFuncAttributeMaxDynamicSharedMemorySize, SMEM_BYTES);

    const dim3 blk(256);
    const long long pn4 = (long long)BATCH * LP * HID / 4;

    // 0) split q and W only (proj_p split rides inside GEMM1)
    split_qw_kernel<<<dim3(2048, 2), 256>>>(proj_q, qh, ql,
                                            (long long)BATCH * LQ * HID / 4,
                                            W, wh, wl, (long long)HID * HID / 4);

    // 1) trans_q = proj_q @ W^T + b -> split fp16 [B*LQ, H]; 3-pass
    //    + 512 splitter CTAs converting proj_p in parallel (FUSE role CTAs)
    {
        const int nx = HID / TN;                       // 8
        const int ntiles = nx * ((BATCH * LQ) / TM);   // 2048
        mm_h16<true, false, true, false, true, 3>
            <<<ntiles + 512, blk, SMEM_BYTES>>>(
            qh, ql, wh, wl, bias, nullptr, tqh, tql, HID, HID, HID, HID,
            0, 0, 0, proj_p, ph, pl, pn4, nx, ntiles);
    }

    // 2) att[b] = proj_p[b] @ trans_q[b]^T  -> fp32 [LP, LQ]; 3-pass
    mm_h16<false, false, false, false, false, 3>
        <<<dim3(LQ / TN, LP / TM, BATCH), blk, SMEM_BYTES>>>(
        ph, pl, tqh, tql, nullptr, att, nullptr, nullptr, HID, HID, HID, LQ,
        (long long)LP * HID, (long long)LQ * HID, (long long)LP * LQ,
        nullptr, nullptr, nullptr, 0, 0, 0);

    // 3) softmax -> fp16 hi only
    softmax_h16<<<BATCH * LP, 256>>>(att, ah);

    // 4) out = relu(att_norm @ trans_q)  — 1-pass plain fp16 (att rows sum
    //    to 1: total error ~3.5e-4 << 1e-3; bias folded; B via ldmatrix.trans)
    mm_h16<false, true, false, true, false, 1>
        <<<dim3(HID / TN, LP / TM, BATCH), blk, SMEM_BYTES>>>(
        ah, nullptr, tqh, nullptr, nullptr, out, nullptr, nullptr, LQ, LQ, HID, HID,
        (long long)LP * LQ, (long long)LQ * HID, (long long)LP * HID,
        nullptr, nullptr, nullptr, 0, 0, 0);
}